// round 3
// baseline (speedup 1.0000x reference)
#include <cuda_runtime.h>

// Problem constants
#define BB   16384
#define TT   25
#define DD   128
#define HH   128
#define GG   512    // 4H
#define KKK  256    // D + H
#define OUTD 128
#define MM   32     // batch rows per CTA
#define NT   512    // threads per CTA

// ---------- packed f32x2 helpers (FFMA2: 2 fp32 FMAs per instruction) ----------
__device__ __forceinline__ unsigned long long pack2f(float lo, float hi) {
    unsigned long long r;
    asm("mov.b64 %0, {%1, %2};" : "=l"(r) : "f"(lo), "f"(hi));
    return r;
}
__device__ __forceinline__ void ffma2(unsigned long long &acc,
                                      unsigned long long a,
                                      unsigned long long b) {
    asm("fma.rn.f32x2 %0, %1, %2, %0;" : "+l"(acc) : "l"(a), "l"(b));
}
__device__ __forceinline__ float hsum2(unsigned long long v) {
    float lo, hi;
    asm("mov.b64 {%0, %1}, %2;" : "=f"(lo), "=f"(hi) : "l"(v));
    return lo + hi;
}

__device__ __forceinline__ float sigmoid_f(float x) {
    return __fdividef(1.f, 1.f + __expf(-x));
}
__device__ __forceinline__ float tanh_f(float x) {
    // 1 - 2/(e^{2x}+1); saturates correctly for large |x| (inf -> 1, 0 -> -1)
    return 1.f - __fdividef(2.f, __expf(2.f * x) + 1.f);
}

__global__ __launch_bounds__(NT, 1)
void lstm_agg_kernel(const float* __restrict__ self_vecs,   // [B, D]
                     const float* __restrict__ neig,        // [B, T, D]
                     const float* __restrict__ Wk,          // [D, 4H]
                     const float* __restrict__ Wr,          // [H, 4H]
                     const float* __restrict__ bias,        // [4H]
                     const float* __restrict__ Wself,       // [D, OUT]
                     const float* __restrict__ Wneigh,      // [H, OUT]
                     float* __restrict__ out)               // [B, OUT]
{
    extern __shared__ float smem[];
    float* Xs   = smem;                   // [MM][KKK]  (x_t | h)   32 KB
    float* Zs   = Xs + MM * KKK;          // [MM][GG]   pre-act     64 KB
    float* Cs   = Zs + MM * GG;           // [MM][HH]   cell state  16 KB
    float* Ho   = Cs + MM * HH;           // [MM][HH]   h snapshot  16 KB
    int*   lenS = (int*)(Ho + MM * HH);   // [MM]

    const int tid  = threadIdx.x;
    const int b0   = blockIdx.x * MM;
    const int wid  = tid >> 5;
    const int lane = tid & 31;

    // ---- prepass: per-row sequence lengths (2 rows per warp, exact semantics) ----
    #pragma unroll
    for (int rr = 0; rr < 2; rr++) {
        const int r = wid * 2 + rr;
        const float4* xrow = (const float4*)(neig + (size_t)(b0 + r) * TT * DD);
        int len = 0;
        for (int t = 0; t < TT; t++) {
            float4 v = xrow[t * (DD / 4) + lane];
            bool nz = (v.x != 0.f) || (v.y != 0.f) || (v.z != 0.f) || (v.w != 0.f);
            len += (__ballot_sync(0xffffffffu, nz) != 0u) ? 1 : 0;
        }
        if (lane == 0) lenS[r] = (len > 0) ? len : 1;
    }

    // ---- init h (in Xs) and c to zero ----
    for (int i = tid; i < MM * HH; i += NT) {
        int r = i >> 7, u = i & 127;
        Xs[r * KKK + DD + u] = 0.f;
        Cs[i] = 0.f;
    }
    __syncthreads();

    const float bias_c = bias[tid];   // this thread's output column bias

    // ---- recurrence over T steps ----
    for (int t = 0; t < TT; t++) {
        // load x_t tile into Xs[:, 0:D] (coalesced float4)
        for (int i = tid; i < MM * (DD / 4); i += NT) {
            int r = i >> 5, q = i & 31;
            ((float4*)(Xs + r * KKK))[q] =
                ((const float4*)(neig + ((size_t)(b0 + r) * TT + t) * DD))[q];
        }
        __syncthreads();

        // GEMM: z[r][tid] = bias + sum_k X[r][k] * W[k][tid], packed f32x2 over k
        unsigned long long acc[MM];
        #pragma unroll
        for (int r = 0; r < MM; r++) acc[r] = pack2f(bias_c, 0.f);

        #pragma unroll
        for (int half = 0; half < 2; half++) {
            const float* Wb  = (half == 0 ? Wk : Wr) + tid;
            const int    xoff = half * DD;
            // software prefetch of the next k-quad's weights
            float w0 = Wb[0], w1 = Wb[GG], w2 = Wb[2 * GG], w3 = Wb[3 * GG];
            #pragma unroll 1
            for (int kq = 0; kq < DD / 4; kq++) {
                float n0 = 0.f, n1 = 0.f, n2 = 0.f, n3 = 0.f;
                if (kq < DD / 4 - 1) {
                    const float* Wn = Wb + 4 * GG;
                    n0 = Wn[0]; n1 = Wn[GG]; n2 = Wn[2 * GG]; n3 = Wn[3 * GG];
                }
                const unsigned long long wp0 = pack2f(w0, w1);
                const unsigned long long wp1 = pack2f(w2, w3);
                const float* xb = Xs + xoff + 4 * kq;
                #pragma unroll
                for (int r = 0; r < MM; r++) {
                    // contiguous k-pairs: one LDS.128 = two packed operands
                    ulonglong2 xv = *reinterpret_cast<const ulonglong2*>(xb + r * KKK);
                    ffma2(acc[r], xv.x, wp0);
                    ffma2(acc[r], xv.y, wp1);
                }
                w0 = n0; w1 = n1; w2 = n2; w3 = n3;
                Wb += 4 * GG;
            }
        }

        #pragma unroll
        for (int r = 0; r < MM; r++) Zs[r * GG + tid] = hsum2(acc[r]);
        __syncthreads();

        // gates + state update (8 (row,unit) pairs per thread, conflict-free)
        #pragma unroll
        for (int j = 0; j < (MM * HH) / NT; j++) {
            int idx = tid + j * NT;
            int r = idx >> 7, u = idx & 127;
            float zi = Zs[r * GG + u];
            float zf = Zs[r * GG + u + HH];
            float zg = Zs[r * GG + u + 2 * HH];
            float zo = Zs[r * GG + u + 3 * HH];
            float iv = sigmoid_f(zi);
            float fv = sigmoid_f(zf);
            float gv = tanh_f(zg);
            float ov = sigmoid_f(zo);
            float c  = fv * Cs[idx] + iv * gv;
            Cs[idx]  = c;
            float h  = ov * tanh_f(c);
            Xs[r * KKK + DD + u] = h;             // next step's recurrent input
            if (t == lenS[r] - 1) Ho[idx] = h;    // hs[length-1] snapshot
        }
        __syncthreads();
    }

    // ---- epilogue: out = relu(self @ Wself + h_sel @ Wneigh) ----
    for (int i = tid; i < MM * (DD / 4); i += NT) {
        int r = i >> 5, q = i & 31;
        ((float4*)(Xs + r * KKK))[q] =
            ((const float4*)(self_vecs + (size_t)(b0 + r) * DD))[q];
    }
    __syncthreads();

    #pragma unroll
    for (int j = 0; j < 2; j++) {
        int idx = tid + j * NT;             // 1024 float4 outputs = 32 rows x 32 groups
        int r   = idx >> 5;
        int o4  = idx & 31;
        float4 a = make_float4(0.f, 0.f, 0.f, 0.f);
        for (int d = 0; d < DD; d++) {
            float x  = Xs[r * KKK + d];
            float4 w = ((const float4*)(Wself + d * OUTD))[o4];
            a.x += x * w.x; a.y += x * w.y; a.z += x * w.z; a.w += x * w.w;
        }
        for (int u = 0; u < HH; u++) {
            float h  = Ho[r * HH + u];
            float4 w = ((const float4*)(Wneigh + u * OUTD))[o4];
            a.x += h * w.x; a.y += h * w.y; a.z += h * w.z; a.w += h * w.w;
        }
        float4* op = ((float4*)(out + (size_t)(b0 + r) * OUTD)) + o4;
        *op = make_float4(fmaxf(a.x, 0.f), fmaxf(a.y, 0.f),
                          fmaxf(a.z, 0.f), fmaxf(a.w, 0.f));
    }
}

extern "C" void kernel_launch(void* const* d_in, const int* in_sizes, int n_in,
                              void* d_out, int out_size) {
    const float* self_vecs = (const float*)d_in[0];
    const float* neig      = (const float*)d_in[1];
    const float* Wk        = (const float*)d_in[2];
    const float* Wr        = (const float*)d_in[3];
    const float* bias      = (const float*)d_in[4];
    const float* Wself     = (const float*)d_in[5];
    const float* Wneigh    = (const float*)d_in[6];
    float* out = (float*)d_out;

    const int smem_bytes = (MM * KKK + MM * GG + 2 * MM * HH) * 4 + MM * 4; // 131200 B
    cudaFuncSetAttribute(lstm_agg_kernel,
                         cudaFuncAttributeMaxDynamicSharedMemorySize, smem_bytes);

    lstm_agg_kernel<<<BB / MM, NT, smem_bytes>>>(
        self_vecs, neig, Wk, Wr, bias, Wself, Wneigh, out);
}

// round 9
// speedup vs baseline: 2.6306x; 2.6306x over previous
#include <cuda_runtime.h>
#include <cstdint>

#define TT 25
#define PA 260   // A smem pitch (floats): 260 % 32 == 4 -> conflict-free frags
#define PC 132   // C smem pitch

__device__ __align__(16) float g_Wt[256 * 512];   // [k][frag-ordered n'] tf32
__device__ __align__(16) float g_We[256 * 128];   // epilogue weights
__device__ float g_Ho[(size_t)16384 * 128];       // h at t = len-1

__device__ __forceinline__ uint32_t tf32r(float v) {
    uint32_t t; asm("cvt.rna.tf32.f32 %0, %1;" : "=r"(t) : "f"(v)); return t;
}
__device__ __forceinline__ float tf32f(float v) { return __uint_as_float(tf32r(v)); }
__device__ __forceinline__ float sigf(float x) { return __fdividef(1.f, 1.f + __expf(-x)); }
__device__ __forceinline__ float thf(float x)  { return 1.f - __fdividef(2.f, __expf(2.f * x) + 1.f); }
__device__ __forceinline__ uint32_t u32(float v) { return __float_as_uint(v); }

__device__ __forceinline__ void mma8(float* d, const uint32_t* a, uint32_t b0, uint32_t b1) {
    asm volatile("mma.sync.aligned.m16n8k8.row.col.f32.tf32.tf32.f32 "
        "{%0,%1,%2,%3},{%4,%5,%6,%7},{%8,%9},{%0,%1,%2,%3};"
        : "+f"(d[0]), "+f"(d[1]), "+f"(d[2]), "+f"(d[3])
        : "r"(a[0]), "r"(a[1]), "r"(a[2]), "r"(a[3]), "r"(b0), "r"(b1));
}

// W -> tf32, gate-interleaved (n' = u*4+g), fragment-ordered [k][nw][ly][j]
__global__ void prep_kernel(const float* __restrict__ Wk, const float* __restrict__ Wr,
                            const float* __restrict__ Ws, const float* __restrict__ Wn) {
    int idx = blockIdx.x * blockDim.x + threadIdx.x;   // 131072 threads
    {
        int k = idx >> 9, pos = idx & 511;
        int nw = pos >> 6, r = pos & 63, ly = r >> 3, j = r & 7;
        int n = nw * 64 + j * 8 + ly;                  // interleaved col index
        int uu = n >> 2, g = n & 3, col = g * 128 + uu;
        float v = (k < 128) ? Wk[k * 512 + col] : Wr[(k - 128) * 512 + col];
        g_Wt[k * 512 + nw * 64 + ly * 8 + j] = tf32f(v);
    }
    if (idx < 256 * 128) {
        int k = idx >> 7, pos = idx & 127;
        int nw = pos >> 5, r = pos & 31, ly = r >> 2, j = r & 3;
        int n = nw * 32 + j * 8 + ly;
        float v = (k < 128) ? Ws[k * 128 + n] : Wn[(k - 128) * 128 + n];
        g_We[k * 128 + nw * 32 + ly * 4 + j] = tf32f(v);
    }
}

#define SMEM_DYN ((128 * PA + 128 * PC + 512 + 128) * 4)

__global__ __launch_bounds__(512, 1)
void lstm_main(const float* __restrict__ self_vecs, const float* __restrict__ neig,
               const float* __restrict__ bias, float* __restrict__ out) {
    extern __shared__ float sm[];
    float* A = sm;                       // [128][PA] : cols 0-127 x_t, 128-255 h
    float* C = sm + 128 * PA;            // [128][PC] cell state
    float* biasP = C + 128 * PC;         // [512] permuted bias
    int* LEN = (int*)(biasP + 512);

    const int tid = threadIdx.x, wid = tid >> 5, lane = tid & 31;
    const int ly = lane >> 2, kx = lane & 3;
    const int b0 = blockIdx.x * 128;

    for (int i = tid; i < 512; i += 512) biasP[i] = bias[(i & 3) * 128 + (i >> 2)];

    // exact sequence lengths: warp w -> rows w*8..w*8+7
    #pragma unroll
    for (int j = 0; j < 8; j++) {
        int r = wid * 8 + j;
        const float4* xp = (const float4*)(neig + (size_t)(b0 + r) * TT * 128) + lane;
        int cnt = 0;
        for (int t = 0; t < TT; t++) {
            float4 v = xp[t * 32];
            bool nz = v.x != 0.f || v.y != 0.f || v.z != 0.f || v.w != 0.f;
            cnt += (__ballot_sync(~0u, nz) != 0u);
        }
        if (lane == 0) LEN[r] = cnt ? cnt : 1;
    }
    for (int i = tid; i < 128 * 128; i += 512) A[(i >> 7) * PA + 128 + (i & 127)] = 0.f;
    for (int i = tid; i < 128 * PC; i += 512) C[i] = 0.f;

    const int mw = wid & 1, nw = wid >> 1;       // main: 2m x 8n warp grid per pass
    const bool owner = (kx & 1) == 0;

    for (int t = 0; t < TT; t++) {
        __syncthreads();
        for (int i = tid; i < 128 * 32; i += 512) {   // x_t -> A cols 0..127
            int r = i >> 5, q = i & 31;
            float4 v = *(const float4*)(neig + ((size_t)(b0 + r) * TT + t) * 128 + q * 4);
            *(float4*)(A + r * PA + q * 4) =
                make_float4(tf32f(v.x), tf32f(v.y), tf32f(v.z), tf32f(v.w));
        }
        __syncthreads();

        #pragma unroll 1
        for (int p = 0; p < 2; p++) {
            const int R0 = p * 64 + mw * 32;
            float acc[2][8][4];
            #pragma unroll
            for (int m = 0; m < 2; m++)
                #pragma unroll
                for (int j = 0; j < 8; j++)
                    #pragma unroll
                    for (int e = 0; e < 4; e++) acc[m][j][e] = 0.f;

            const float* bp = g_Wt + kx * 512 + nw * 64 + ly * 8;
            float4 nb00 = *(const float4*)bp,          nb01 = *(const float4*)(bp + 4);
            float4 nb10 = *(const float4*)(bp + 2048), nb11 = *(const float4*)(bp + 2052);

            #pragma unroll 1
            for (int c = 0; c < 32; c++) {
                float4 b00 = nb00, b01 = nb01, b10 = nb10, b11 = nb11;
                if (c < 31) {
                    const float* np = bp + (c + 1) * 4096;
                    nb00 = *(const float4*)np;          nb01 = *(const float4*)(np + 4);
                    nb10 = *(const float4*)(np + 2048); nb11 = *(const float4*)(np + 2052);
                }
                const float* ap = A + (R0 + ly) * PA + c * 8 + kx;
                uint32_t af0[4], af1[4];
                af0[0] = u32(ap[0]);       af0[1] = u32(ap[8 * PA]);
                af0[2] = u32(ap[4]);       af0[3] = u32(ap[8 * PA + 4]);
                af1[0] = u32(ap[16 * PA]); af1[1] = u32(ap[24 * PA]);
                af1[2] = u32(ap[16 * PA + 4]); af1[3] = u32(ap[24 * PA + 4]);
                uint32_t B0[8] = {u32(b00.x), u32(b00.y), u32(b00.z), u32(b00.w),
                                  u32(b01.x), u32(b01.y), u32(b01.z), u32(b01.w)};
                uint32_t B1[8] = {u32(b10.x), u32(b10.y), u32(b10.z), u32(b10.w),
                                  u32(b11.x), u32(b11.y), u32(b11.z), u32(b11.w)};
                #pragma unroll
                for (int j = 0; j < 8; j++) {
                    mma8(acc[0][j], af0, B0[j], B1[j]);
                    mma8(acc[1][j], af1, B0[j], B1[j]);
                }
            }
            __syncthreads();   // all A reads done before h writes

            #pragma unroll
            for (int mt = 0; mt < 2; mt++) {
                #pragma unroll
                for (int rh = 0; rh < 2; rh++) {
                    const int row = R0 + mt * 16 + rh * 8 + ly;
                    const int len1 = LEN[row] - 1;
                    #pragma unroll
                    for (int j = 0; j < 8; j++) {
                        const int n0 = nw * 64 + j * 8 + 2 * kx;
                        float z0 = acc[mt][j][rh * 2]     + biasP[n0];
                        float z1 = acc[mt][j][rh * 2 + 1] + biasP[n0 + 1];
                        float a1 = owner ? sigf(z0) : thf(z0);  // i | g
                        float a2 = sigf(z1);                    // f | o
                        float x1 = __shfl_xor_sync(~0u, a1, 1);
                        float x2 = __shfl_xor_sync(~0u, a2, 1);
                        if (owner) {
                            const int uu = n0 >> 2;
                            float cc = a2 * C[row * PC + uu] + a1 * x1;  // f*c + i*g
                            C[row * PC + uu] = cc;
                            float h = x2 * thf(cc);                     // o * tanh(c)
                            A[row * PA + 128 + uu] = tf32f(h);
                            if (t == len1) g_Ho[(size_t)(b0 + row) * 128 + uu] = h;
                        }
                    }
                }
            }
        }
    }
    __syncthreads();

    // ---- output GEMM: out = relu([self | h_sel] @ We) ----
    for (int i = tid; i < 128 * 32; i += 512) {
        int r = i >> 5, q = i & 31;
        float4 v = *(const float4*)(self_vecs + (size_t)(b0 + r) * 128 + q * 4);
        *(float4*)(A + r * PA + q * 4) =
            make_float4(tf32f(v.x), tf32f(v.y), tf32f(v.z), tf32f(v.w));
        float4 h = *(const float4*)(g_Ho + (size_t)(b0 + r) * 128 + q * 4);
        *(float4*)(A + r * PA + 128 + q * 4) =
            make_float4(tf32f(h.x), tf32f(h.y), tf32f(h.z), tf32f(h.w));
    }
    __syncthreads();

    const int mw2 = wid & 3, nw2 = wid >> 2;   // 4m x 4n warp grid
    const int R2 = mw2 * 32;
    float ac2[2][4][4];
    #pragma unroll
    for (int m = 0; m < 2; m++)
        #pragma unroll
        for (int j = 0; j < 4; j++)
            #pragma unroll
            for (int e = 0; e < 4; e++) ac2[m][j][e] = 0.f;

    #pragma unroll 1
    for (int c = 0; c < 32; c++) {
        const float* bp = g_We + (c * 8 + kx) * 128 + nw2 * 32 + ly * 4;
        float4 q0 = *(const float4*)bp;
        float4 q1 = *(const float4*)(bp + 4 * 128);
        uint32_t B0[4] = {u32(q0.x), u32(q0.y), u32(q0.z), u32(q0.w)};
        uint32_t B1[4] = {u32(q1.x), u32(q1.y), u32(q1.z), u32(q1.w)};
        const float* ap = A + (R2 + ly) * PA + c * 8 + kx;
        uint32_t af0[4], af1[4];
        af0[0] = u32(ap[0]);       af0[1] = u32(ap[8 * PA]);
        af0[2] = u32(ap[4]);       af0[3] = u32(ap[8 * PA + 4]);
        af1[0] = u32(ap[16 * PA]); af1[1] = u32(ap[24 * PA]);
        af1[2] = u32(ap[16 * PA + 4]); af1[3] = u32(ap[24 * PA + 4]);
        #pragma unroll
        for (int j = 0; j < 4; j++) {
            mma8(ac2[0][j], af0, B0[j], B1[j]);
            mma8(ac2[1][j], af1, B0[j], B1[j]);
        }
    }
    #pragma unroll
    for (int mt = 0; mt < 2; mt++)
        #pragma unroll
        for (int j = 0; j < 4; j++)
            #pragma unroll
            for (int rh = 0; rh < 2; rh++) {
                int row = R2 + mt * 16 + rh * 8 + ly;
                int col = nw2 * 32 + j * 8 + 2 * kx;
                float2 o;
                o.x = fmaxf(ac2[mt][j][rh * 2], 0.f);
                o.y = fmaxf(ac2[mt][j][rh * 2 + 1], 0.f);
                *(float2*)(out + (size_t)(b0 + row) * 128 + col) = o;
            }
}

extern "C" void kernel_launch(void* const* d_in, const int* in_sizes, int n_in,
                              void* d_out, int out_size) {
    prep_kernel<<<256, 512>>>((const float*)d_in[2], (const float*)d_in[3],
                              (const float*)d_in[5], (const float*)d_in[6]);
    cudaFuncSetAttribute(lstm_main, cudaFuncAttributeMaxDynamicSharedMemorySize, SMEM_DYN);
    lstm_main<<<128, 512, SMEM_DYN>>>((const float*)d_in[0], (const float*)d_in[1],
                                      (const float*)d_in[4], (float*)d_out);
}

// round 10
// speedup vs baseline: 2.9161x; 1.1085x over previous
#include <cuda_runtime.h>
#include <cstdint>

#define TT 25
#define PA 260   // A smem pitch (floats): 260 % 32 == 4 -> conflict-free frags
#define PC 132   // C smem pitch

__device__ __align__(16) float g_Wt[256 * 512];   // [k][frag-ordered n'] tf32 (k<128: Wr, k>=128: Wk)
__device__ __align__(16) float g_We[256 * 128];   // epilogue weights
__device__ float g_Ho[(size_t)16384 * 128];       // h at t = len-1

__device__ __forceinline__ uint32_t tf32r(float v) {
    uint32_t t; asm("cvt.rna.tf32.f32 %0, %1;" : "=r"(t) : "f"(v)); return t;
}
__device__ __forceinline__ float tf32f(float v) { return __uint_as_float(tf32r(v)); }
__device__ __forceinline__ float sigf(float x) { return __fdividef(1.f, 1.f + __expf(-x)); }
__device__ __forceinline__ float thf(float x)  { return 1.f - __fdividef(2.f, __expf(2.f * x) + 1.f); }
__device__ __forceinline__ uint32_t u32(float v) { return __float_as_uint(v); }
__device__ __forceinline__ uint32_t smem_u32(const void* p) {
    uint32_t a;
    asm("{.reg .u64 t; cvta.to.shared.u64 t, %1; cvt.u32.u64 %0, t;}" : "=r"(a) : "l"(p));
    return a;
}
__device__ __forceinline__ void cp16(uint32_t dst, const float* src) {
    asm volatile("cp.async.ca.shared.global [%0],[%1],16;" :: "r"(dst), "l"(src) : "memory");
}
#define CP_COMMIT() asm volatile("cp.async.commit_group;" ::: "memory")
#define CP_WAIT0()  asm volatile("cp.async.wait_group 0;" ::: "memory")

__device__ __forceinline__ void mma8(float* d, const uint32_t* a, uint32_t b0, uint32_t b1) {
    asm volatile("mma.sync.aligned.m16n8k8.row.col.f32.tf32.tf32.f32 "
        "{%0,%1,%2,%3},{%4,%5,%6,%7},{%8,%9},{%0,%1,%2,%3};"
        : "+f"(d[0]), "+f"(d[1]), "+f"(d[2]), "+f"(d[3])
        : "r"(a[0]), "r"(a[1]), "r"(a[2]), "r"(a[3]), "r"(b0), "r"(b1));
}

// W -> tf32, gate-interleaved (n' = u*4+g), fragment-ordered [k][nw][ly][j]
// k-halves swapped: k<128 -> Wr[k] (h part), k>=128 -> Wk[k-128] (x part)
__global__ void prep_kernel(const float* __restrict__ Wk, const float* __restrict__ Wr,
                            const float* __restrict__ Ws, const float* __restrict__ Wn) {
    int idx = blockIdx.x * blockDim.x + threadIdx.x;   // 131072 threads
    {
        int k = idx >> 9, pos = idx & 511;
        int nw = pos >> 6, r = pos & 63, ly = r >> 3, j = r & 7;
        int n = nw * 64 + j * 8 + ly;
        int uu = n >> 2, g = n & 3, col = g * 128 + uu;
        float v = (k < 128) ? Wr[k * 512 + col] : Wk[(k - 128) * 512 + col];
        g_Wt[k * 512 + nw * 64 + ly * 8 + j] = tf32f(v);
    }
    if (idx < 256 * 128) {
        int k = idx >> 7, pos = idx & 127;
        int nw = pos >> 5, r = pos & 31, ly = r >> 2, j = r & 3;
        int n = nw * 32 + j * 8 + ly;
        float v = (k < 128) ? Ws[k * 128 + n] : Wn[(k - 128) * 128 + n];
        g_We[k * 128 + nw * 32 + ly * 4 + j] = tf32f(v);
    }
}

#define SMEM_DYN ((128 * PA + 128 * PC + 512 + 128) * 4)

__global__ __launch_bounds__(512, 1)
void lstm_main(const float* __restrict__ self_vecs, const float* __restrict__ neig,
               const float* __restrict__ bias, float* __restrict__ out) {
    extern __shared__ float sm[];
    float* A = sm;                       // [128][PA] : cols 0-127 h, 128-255 x_t
    float* C = sm + 128 * PA;            // [128][PC] cell state
    float* biasP = C + 128 * PC;         // [512] permuted bias
    int* LEN = (int*)(biasP + 512);
    const uint32_t As = smem_u32(A);

    const int tid = threadIdx.x, wid = tid >> 5, lane = tid & 31;
    const int ly = lane >> 2, kx = lane & 3;
    const int b0 = blockIdx.x * 128;

    // prefetch x_0 into A cols 128..255 (raw fp32 -> tf32 truncation in mma)
    #pragma unroll
    for (int j = 0; j < 8; j++) {
        int i = tid + j * 512;
        int r = i >> 5, q = i & 31;
        cp16(As + (uint32_t)(r * PA + 128 + q * 4) * 4u,
             neig + ((size_t)(b0 + r) * TT) * 128 + q * 4);
    }
    CP_COMMIT();

    for (int i = tid; i < 512; i += 512) biasP[i] = bias[(i & 3) * 128 + (i >> 2)];

    // exact sequence lengths: warp w -> rows w*8..w*8+7
    #pragma unroll
    for (int j = 0; j < 8; j++) {
        int r = wid * 8 + j;
        const float4* xp = (const float4*)(neig + (size_t)(b0 + r) * TT * 128) + lane;
        int cnt = 0;
        for (int t = 0; t < TT; t++) {
            float4 v = xp[t * 32];
            bool nz = v.x != 0.f || v.y != 0.f || v.z != 0.f || v.w != 0.f;
            cnt += (__ballot_sync(~0u, nz) != 0u);
        }
        if (lane == 0) LEN[r] = cnt ? cnt : 1;
    }
    for (int i = tid; i < 128 * 128; i += 512) A[(i >> 7) * PA + (i & 127)] = 0.f;  // h = 0
    for (int i = tid; i < 128 * PC; i += 512) C[i] = 0.f;

    const int mw = wid & 1, nw = wid >> 1;   // main: 2m x 8n warp grid per pass
    const bool evenlane = (kx & 1) == 0;

    for (int t = 0; t < TT; t++) {
        CP_WAIT0();
        __syncthreads();

        #pragma unroll 1
        for (int p = 0; p < 2; p++) {
            const int R0 = p * 64 + mw * 32;
            float acc[2][8][4];
            #pragma unroll
            for (int m = 0; m < 2; m++)
                #pragma unroll
                for (int j = 0; j < 8; j++)
                    #pragma unroll
                    for (int e = 0; e < 4; e++) acc[m][j][e] = 0.f;

            const float* bp = g_Wt + kx * 512 + nw * 64 + ly * 8;
            float4 nb00 = *(const float4*)bp,          nb01 = *(const float4*)(bp + 4);
            float4 nb10 = *(const float4*)(bp + 2048), nb11 = *(const float4*)(bp + 2052);

            #pragma unroll 1
            for (int c = 0; c < 32; c++) {
                float4 b00 = nb00, b01 = nb01, b10 = nb10, b11 = nb11;
                if (c < 31) {
                    const float* np = bp + (c + 1) * 4096;
                    nb00 = *(const float4*)np;          nb01 = *(const float4*)(np + 4);
                    nb10 = *(const float4*)(np + 2048); nb11 = *(const float4*)(np + 2052);
                }
                const float* ap = A + (R0 + ly) * PA + c * 8 + kx;
                uint32_t af0[4], af1[4];
                af0[0] = u32(ap[0]);       af0[1] = u32(ap[8 * PA]);
                af0[2] = u32(ap[4]);       af0[3] = u32(ap[8 * PA + 4]);
                af1[0] = u32(ap[16 * PA]); af1[1] = u32(ap[24 * PA]);
                af1[2] = u32(ap[16 * PA + 4]); af1[3] = u32(ap[24 * PA + 4]);
                uint32_t B0[8] = {u32(b00.x), u32(b00.y), u32(b00.z), u32(b00.w),
                                  u32(b01.x), u32(b01.y), u32(b01.z), u32(b01.w)};
                uint32_t B1[8] = {u32(b10.x), u32(b10.y), u32(b10.z), u32(b10.w),
                                  u32(b11.x), u32(b11.y), u32(b11.z), u32(b11.w)};
                #pragma unroll
                for (int j = 0; j < 8; j++) {
                    mma8(acc[0][j], af0, B0[j], B1[j]);
                    mma8(acc[1][j], af1, B0[j], B1[j]);
                }
            }
            __syncthreads();   // all A reads of this pass done

            // after the LAST reader of x_t: prefetch x_{t+1} (overlaps epilogue below)
            if (p == 1 && t + 1 < TT) {
                #pragma unroll
                for (int j = 0; j < 8; j++) {
                    int i = tid + j * 512;
                    int r = i >> 5, q = i & 31;
                    cp16(As + (uint32_t)(r * PA + 128 + q * 4) * 4u,
                         neig + ((size_t)(b0 + r) * TT + (t + 1)) * 128 + q * 4);
                }
                CP_COMMIT();
            }

            // ---- parity-split epilogue: even lanes -> rh0 rows, odd -> rh1 rows ----
            #pragma unroll
            for (int mt = 0; mt < 2; mt++) {
                #pragma unroll
                for (int j = 0; j < 8; j++) {
                    const int n0 = nw * 64 + j * 8 + 2 * kx;
                    const float bz0 = biasP[n0], bz1 = biasP[n0 + 1];
                    float z00 = acc[mt][j][0] + bz0;   // rh0, first gate of pair
                    float z01 = acc[mt][j][1] + bz1;
                    float z10 = acc[mt][j][2] + bz0;   // rh1
                    float z11 = acc[mt][j][3] + bz1;
                    float a00, a01, a10, a11;
                    if (evenlane) {  // (i, f)
                        a00 = sigf(z00); a01 = sigf(z01);
                        a10 = sigf(z10); a11 = sigf(z11);
                    } else {         // (g, o)
                        a00 = thf(z00);  a01 = sigf(z01);
                        a10 = thf(z10);  a11 = sigf(z11);
                    }
                    float s1 = evenlane ? a10 : a00;
                    float s2 = evenlane ? a11 : a01;
                    float r1 = __shfl_xor_sync(~0u, s1, 1);
                    float r2 = __shfl_xor_sync(~0u, s2, 1);
                    float iv, fv, gv, ov; int rr;
                    if (evenlane) { iv = a00; fv = a01; gv = r1; ov = r2; rr = R0 + mt * 16 + ly; }
                    else          { iv = r1;  fv = r2;  gv = a10; ov = a11; rr = R0 + mt * 16 + 8 + ly; }
                    const int uu = nw * 16 + j * 2 + (kx >> 1);
                    float cc = fv * C[rr * PC + uu] + iv * gv;
                    C[rr * PC + uu] = cc;
                    float h = ov * thf(cc);
                    A[rr * PA + uu] = tf32f(h);
                    if (t == LEN[rr] - 1) g_Ho[(size_t)(b0 + rr) * 128 + uu] = h;
                }
            }
        }
    }
    __syncthreads();

    // ---- output GEMM: out = relu([self | h_sel] @ We) ----
    for (int i = tid; i < 128 * 32; i += 512) {
        int r = i >> 5, q = i & 31;
        float4 v = *(const float4*)(self_vecs + (size_t)(b0 + r) * 128 + q * 4);
        *(float4*)(A + r * PA + q * 4) =
            make_float4(tf32f(v.x), tf32f(v.y), tf32f(v.z), tf32f(v.w));
        float4 h = *(const float4*)(g_Ho + (size_t)(b0 + r) * 128 + q * 4);
        *(float4*)(A + r * PA + 128 + q * 4) =
            make_float4(tf32f(h.x), tf32f(h.y), tf32f(h.z), tf32f(h.w));
    }
    __syncthreads();

    const int mw2 = wid & 3, nw2 = wid >> 2;   // 4m x 4n warp grid
    const int R2 = mw2 * 32;
    float ac2[2][4][4];
    #pragma unroll
    for (int m = 0; m < 2; m++)
        #pragma unroll
        for (int j = 0; j < 4; j++)
            #pragma unroll
            for (int e = 0; e < 4; e++) ac2[m][j][e] = 0.f;

    #pragma unroll 1
    for (int c = 0; c < 32; c++) {
        const float* bp = g_We + (c * 8 + kx) * 128 + nw2 * 32 + ly * 4;
        float4 q0 = *(const float4*)bp;
        float4 q1 = *(const float4*)(bp + 4 * 128);
        uint32_t B0[4] = {u32(q0.x), u32(q0.y), u32(q0.z), u32(q0.w)};
        uint32_t B1[4] = {u32(q1.x), u32(q1.y), u32(q1.z), u32(q1.w)};
        const float* ap = A + (R2 + ly) * PA + c * 8 + kx;
        uint32_t af0[4], af1[4];
        af0[0] = u32(ap[0]);       af0[1] = u32(ap[8 * PA]);
        af0[2] = u32(ap[4]);       af0[3] = u32(ap[8 * PA + 4]);
        af1[0] = u32(ap[16 * PA]); af1[1] = u32(ap[24 * PA]);
        af1[2] = u32(ap[16 * PA + 4]); af1[3] = u32(ap[24 * PA + 4]);
        #pragma unroll
        for (int j = 0; j < 4; j++) {
            mma8(ac2[0][j], af0, B0[j], B1[j]);
            mma8(ac2[1][j], af1, B0[j], B1[j]);
        }
    }
    #pragma unroll
    for (int mt = 0; mt < 2; mt++)
        #pragma unroll
        for (int j = 0; j < 4; j++)
            #pragma unroll
            for (int rh = 0; rh < 2; rh++) {
                int row = R2 + mt * 16 + rh * 8 + ly;
                int col = nw2 * 32 + j * 8 + 2 * kx;
                float2 o;
                o.x = fmaxf(ac2[mt][j][rh * 2], 0.f);
                o.y = fmaxf(ac2[mt][j][rh * 2 + 1], 0.f);
                *(float2*)(out + (size_t)(b0 + row) * 128 + col) = o;
            }
}

extern "C" void kernel_launch(void* const* d_in, const int* in_sizes, int n_in,
                              void* d_out, int out_size) {
    prep_kernel<<<256, 512>>>((const float*)d_in[2], (const float*)d_in[3],
                              (const float*)d_in[5], (const float*)d_in[6]);
    cudaFuncSetAttribute(lstm_main, cudaFuncAttributeMaxDynamicSharedMemorySize, SMEM_DYN);
    lstm_main<<<128, 512, SMEM_DYN>>>((const float*)d_in[0], (const float*)d_in[1],
                                      (const float*)d_in[4], (float*)d_out);
}

// round 11
// speedup vs baseline: 3.4437x; 1.1809x over previous
#include <cuda_runtime.h>
#include <cstdint>

#define TT 25
#define PA 260   // A smem pitch (floats), 260 % 32 == 4 -> conflict-free frags
#define PC 132   // C smem pitch
#define PX 132   // x smem pitch (phase 1)

__device__ __align__(16) float g_Wk2[128 * 512];  // phase-1 weights, lane-major frag layout
__device__ __align__(16) float g_Wr2[128 * 512];  // recurrent weights, lane-major frag layout
__device__ __align__(16) float g_We[256 * 128];   // output weights (frag-ordered)
__device__ float g_Ho[(size_t)16384 * 128];       // h at t = len-1
__device__ float g_XW[(size_t)16384 * TT * 512];  // x@Wk in accumulator-fragment layout

__device__ __forceinline__ uint32_t tf32r(float v) {
    uint32_t t; asm("cvt.rna.tf32.f32 %0, %1;" : "=r"(t) : "f"(v)); return t;
}
__device__ __forceinline__ float tf32f(float v) { return __uint_as_float(tf32r(v)); }
__device__ __forceinline__ float sigf(float x) { return __fdividef(1.f, 1.f + __expf(-x)); }
__device__ __forceinline__ float thf(float x)  { return 1.f - __fdividef(2.f, __expf(2.f * x) + 1.f); }
__device__ __forceinline__ uint32_t u32(float v) { return __float_as_uint(v); }
__device__ __forceinline__ uint32_t smem_u32(const void* p) {
    uint32_t a;
    asm("{.reg .u64 t; cvta.to.shared.u64 t, %1; cvt.u32.u64 %0, t;}" : "=r"(a) : "l"(p));
    return a;
}
__device__ __forceinline__ void cp16(uint32_t dst, const float* src) {
    asm volatile("cp.async.ca.shared.global [%0],[%1],16;" :: "r"(dst), "l"(src) : "memory");
}
#define CP_COMMIT() asm volatile("cp.async.commit_group;" ::: "memory")
#define CP_WAIT0()  asm volatile("cp.async.wait_group 0;" ::: "memory")

__device__ __forceinline__ void mma8(float* d, const uint32_t* a, uint32_t b0, uint32_t b1) {
    asm volatile("mma.sync.aligned.m16n8k8.row.col.f32.tf32.tf32.f32 "
        "{%0,%1,%2,%3},{%4,%5,%6,%7},{%8,%9},{%0,%1,%2,%3};"
        : "+f"(d[0]), "+f"(d[1]), "+f"(d[2]), "+f"(d[3])
        : "r"(a[0]), "r"(a[1]), "r"(a[2]), "r"(a[3]), "r"(b0), "r"(b1));
}

// Lane-major frag layout for K=128 weights: flat f = (((c*4+q)*8+nw)*32+lane)*4+e.
// q=0 -> B0[e], q=1 -> B0[e+4], q=2 -> B1[e], q=3 -> B1[e+4].
// Gate-interleaved logical col: n' = nw*64 + j*8 + ly, source col = (n'&3)*128 + (n'>>2).
__global__ void prep_kernel(const float* __restrict__ Wk, const float* __restrict__ Wr,
                            const float* __restrict__ Ws, const float* __restrict__ Wn) {
    int f = blockIdx.x * blockDim.x + threadIdx.x;   // 65536 threads
    {
        int c = f >> 12, q = (f >> 10) & 3, nw = (f >> 7) & 7, lane = (f >> 2) & 31, e = f & 3;
        int ly = lane >> 2, kx = lane & 3;
        int k = c * 8 + kx + ((q >> 1) << 2);
        int j = (q & 1) ? e + 4 : e;
        int n = nw * 64 + j * 8 + ly;
        int col = (n & 3) * 128 + (n >> 2);
        g_Wk2[f] = tf32f(Wk[k * 512 + col]);
        g_Wr2[f] = tf32f(Wr[k * 512 + col]);
    }
    if (f < 256 * 128) {
        int k = f >> 7, pos = f & 127;
        int nw = pos >> 5, r = pos & 31, ly = r >> 2, j = r & 3;
        int n = nw * 32 + j * 8 + ly;
        float v = (k < 128) ? Ws[k * 128 + n] : Wn[(k - 128) * 128 + n];
        g_We[k * 128 + nw * 32 + ly * 4 + j] = tf32f(v);
    }
}

// ---------------- phase 1: g_XW = x_t @ Wk for all (b, t), stored as acc frags ----------------
__global__ __launch_bounds__(512, 1)
void xw_kernel(const float* __restrict__ neig) {
    extern __shared__ float X[];   // [128][PX]
    const int tid = threadIdx.x, wid = tid >> 5, lane = tid & 31;
    const int ly = lane >> 2, kx = lane & 3;
    const int bb = blockIdx.x, t = blockIdx.y, b0 = bb * 128;
    const uint32_t Xs = smem_u32(X);

    #pragma unroll
    for (int j2 = 0; j2 < 8; j2++) {
        int i = tid + j2 * 512;
        int r = i >> 5, q = i & 31;
        cp16(Xs + (uint32_t)(r * PX + q * 4) * 4u,
             neig + ((size_t)(b0 + r) * TT + t) * 128 + q * 4);
    }
    CP_COMMIT(); CP_WAIT0();
    __syncthreads();

    const int mw = wid & 1, nw = wid >> 1;
    #pragma unroll 1
    for (int p = 0; p < 2; p++) {
        const int R0 = p * 64 + mw * 32;
        float acc[2][8][4];
        #pragma unroll
        for (int m = 0; m < 2; m++)
            #pragma unroll
            for (int j = 0; j < 8; j++)
                #pragma unroll
                for (int e = 0; e < 4; e++) acc[m][j][e] = 0.f;

        const float* wp = g_Wk2 + nw * 128 + lane * 4;
        float4 n0 = *(const float4*)wp,            n1 = *(const float4*)(wp + 1024);
        float4 n2 = *(const float4*)(wp + 2048),   n3 = *(const float4*)(wp + 3072);
        #pragma unroll 1
        for (int c = 0; c < 16; c++) {
            float4 b0v = n0, b1v = n1, b2v = n2, b3v = n3;
            if (c < 15) {
                const float* np = wp + (c + 1) * 4096;
                n0 = *(const float4*)np;            n1 = *(const float4*)(np + 1024);
                n2 = *(const float4*)(np + 2048);   n3 = *(const float4*)(np + 3072);
            }
            const float* ap = X + (R0 + ly) * PX + c * 8 + kx;
            uint32_t af0[4] = {u32(ap[0]), u32(ap[8 * PX]), u32(ap[4]), u32(ap[8 * PX + 4])};
            uint32_t af1[4] = {u32(ap[16 * PX]), u32(ap[24 * PX]),
                               u32(ap[16 * PX + 4]), u32(ap[24 * PX + 4])};
            uint32_t B0[8] = {u32(b0v.x), u32(b0v.y), u32(b0v.z), u32(b0v.w),
                              u32(b1v.x), u32(b1v.y), u32(b1v.z), u32(b1v.w)};
            uint32_t B1[8] = {u32(b2v.x), u32(b2v.y), u32(b2v.z), u32(b2v.w),
                              u32(b3v.x), u32(b3v.y), u32(b3v.z), u32(b3v.w)};
            #pragma unroll
            for (int j = 0; j < 8; j++) {
                mma8(acc[0][j], af0, B0[j], B1[j]);
                mma8(acc[1][j], af1, B0[j], B1[j]);
            }
        }
        float* op = g_XW + ((((size_t)bb * TT + t) * 2 + p) * 16 + wid) * 2048 + lane * 4;
        #pragma unroll
        for (int i = 0; i < 16; i++)
            *(float4*)(op + i * 128) = make_float4(acc[i >> 3][i & 7][0], acc[i >> 3][i & 7][1],
                                                   acc[i >> 3][i & 7][2], acc[i >> 3][i & 7][3]);
    }
}

#define SMEM_DYN ((128 * PA + 128 * PC + 512 + 128) * 4)

// ---------------- phase 2: recurrence z = xW + h@Wr, gates, output GEMM ----------------
__global__ __launch_bounds__(512, 1)
void lstm_main(const float* __restrict__ self_vecs, const float* __restrict__ neig,
               const float* __restrict__ bias, float* __restrict__ out) {
    extern __shared__ float sm[];
    float* A = sm;                       // [128][PA] : cols 0-127 h (recurrence), 0-255 (output GEMM)
    float* C = sm + 128 * PA;            // [128][PC] cell state
    float* biasP = C + 128 * PC;         // [512] permuted bias
    int* LEN = (int*)(biasP + 512);

    const int tid = threadIdx.x, wid = tid >> 5, lane = tid & 31;
    const int ly = lane >> 2, kx = lane & 3;
    const int bb = blockIdx.x, b0 = bb * 128;

    for (int i = tid; i < 512; i += 512) biasP[i] = bias[(i & 3) * 128 + (i >> 2)];

    // exact sequence lengths: warp w -> rows w*8..w*8+7
    #pragma unroll
    for (int j = 0; j < 8; j++) {
        int r = wid * 8 + j;
        const float4* xp = (const float4*)(neig + (size_t)(b0 + r) * TT * 128) + lane;
        int cnt = 0;
        for (int t = 0; t < TT; t++) {
            float4 v = xp[t * 32];
            bool nz = v.x != 0.f || v.y != 0.f || v.z != 0.f || v.w != 0.f;
            cnt += (__ballot_sync(~0u, nz) != 0u);
        }
        if (lane == 0) LEN[r] = cnt ? cnt : 1;
    }
    for (int i = tid; i < 128 * 128; i += 512) A[(i >> 7) * PA + (i & 127)] = 0.f;  // h = 0
    for (int i = tid; i < 128 * PC; i += 512) C[i] = 0.f;

    const int mw = wid & 1, nw = wid >> 1;
    const bool evenlane = (kx & 1) == 0;

    for (int t = 0; t < TT; t++) {
        __syncthreads();
        #pragma unroll 1
        for (int p = 0; p < 2; p++) {
            const int R0 = p * 64 + mw * 32;
            // acc init = precomputed x_t@Wk fragment
            float acc[2][8][4];
            {
                const float* xp = g_XW + ((((size_t)bb * TT + t) * 2 + p) * 16 + wid) * 2048
                                + lane * 4;
                #pragma unroll
                for (int i = 0; i < 16; i++) {
                    float4 v = *(const float4*)(xp + i * 128);
                    acc[i >> 3][i & 7][0] = v.x; acc[i >> 3][i & 7][1] = v.y;
                    acc[i >> 3][i & 7][2] = v.z; acc[i >> 3][i & 7][3] = v.w;
                }
            }
            const float* wp = g_Wr2 + nw * 128 + lane * 4;
            float4 n0 = *(const float4*)wp,            n1 = *(const float4*)(wp + 1024);
            float4 n2 = *(const float4*)(wp + 2048),   n3 = *(const float4*)(wp + 3072);
            #pragma unroll 1
            for (int c = 0; c < 16; c++) {
                float4 b0v = n0, b1v = n1, b2v = n2, b3v = n3;
                if (c < 15) {
                    const float* np = wp + (c + 1) * 4096;
                    n0 = *(const float4*)np;            n1 = *(const float4*)(np + 1024);
                    n2 = *(const float4*)(np + 2048);   n3 = *(const float4*)(np + 3072);
                }
                const float* ap = A + (R0 + ly) * PA + c * 8 + kx;
                uint32_t af0[4] = {u32(ap[0]), u32(ap[8 * PA]), u32(ap[4]), u32(ap[8 * PA + 4])};
                uint32_t af1[4] = {u32(ap[16 * PA]), u32(ap[24 * PA]),
                                   u32(ap[16 * PA + 4]), u32(ap[24 * PA + 4])};
                uint32_t B0[8] = {u32(b0v.x), u32(b0v.y), u32(b0v.z), u32(b0v.w),
                                  u32(b1v.x), u32(b1v.y), u32(b1v.z), u32(b1v.w)};
                uint32_t B1[8] = {u32(b2v.x), u32(b2v.y), u32(b2v.z), u32(b2v.w),
                                  u32(b3v.x), u32(b3v.y), u32(b3v.z), u32(b3v.w)};
                #pragma unroll
                for (int j = 0; j < 8; j++) {
                    mma8(acc[0][j], af0, B0[j], B1[j]);
                    mma8(acc[1][j], af1, B0[j], B1[j]);
                }
            }
            __syncthreads();   // all A (h) reads of this pass done before h writes

            // ---- parity-split gate epilogue: even lanes -> rh0 rows, odd -> rh1 rows ----
            #pragma unroll
            for (int mt = 0; mt < 2; mt++) {
                #pragma unroll
                for (int j = 0; j < 8; j++) {
                    const int nn0 = nw * 64 + j * 8 + 2 * kx;
                    const float bz0 = biasP[nn0], bz1 = biasP[nn0 + 1];
                    float z00 = acc[mt][j][0] + bz0;
                    float z01 = acc[mt][j][1] + bz1;
                    float z10 = acc[mt][j][2] + bz0;
                    float z11 = acc[mt][j][3] + bz1;
                    float a00, a01, a10, a11;
                    if (evenlane) { a00 = sigf(z00); a01 = sigf(z01); a10 = sigf(z10); a11 = sigf(z11); }
                    else          { a00 = thf(z00);  a01 = sigf(z01); a10 = thf(z10);  a11 = sigf(z11); }
                    float s1 = evenlane ? a10 : a00;
                    float s2 = evenlane ? a11 : a01;
                    float r1 = __shfl_xor_sync(~0u, s1, 1);
                    float r2 = __shfl_xor_sync(~0u, s2, 1);
                    float iv, fv, gv, ov; int rr;
                    if (evenlane) { iv = a00; fv = a01; gv = r1; ov = r2; rr = R0 + mt * 16 + ly; }
                    else          { iv = r1;  fv = r2;  gv = a10; ov = a11; rr = R0 + mt * 16 + 8 + ly; }
                    const int uu = nw * 16 + j * 2 + (kx >> 1);
                    float cc = fv * C[rr * PC + uu] + iv * gv;
                    C[rr * PC + uu] = cc;
                    float h = ov * thf(cc);
                    A[rr * PA + uu] = tf32f(h);
                    if (t == LEN[rr] - 1) g_Ho[(size_t)(b0 + rr) * 128 + uu] = h;
                }
            }
        }
    }
    __syncthreads();

    // ---- output GEMM: out = relu([self | h_sel] @ We) ----
    for (int i = tid; i < 128 * 32; i += 512) {
        int r = i >> 5, q = i & 31;
        float4 v = *(const float4*)(self_vecs + (size_t)(b0 + r) * 128 + q * 4);
        *(float4*)(A + r * PA + q * 4) =
            make_float4(tf32f(v.x), tf32f(v.y), tf32f(v.z), tf32f(v.w));
        float4 h = *(const float4*)(g_Ho + (size_t)(b0 + r) * 128 + q * 4);
        *(float4*)(A + r * PA + 128 + q * 4) =
            make_float4(tf32f(h.x), tf32f(h.y), tf32f(h.z), tf32f(h.w));
    }
    __syncthreads();

    const int mw2 = wid & 3, nw2 = wid >> 2;   // 4m x 4n warp grid
    const int R2 = mw2 * 32;
    float ac2[2][4][4];
    #pragma unroll
    for (int m = 0; m < 2; m++)
        #pragma unroll
        for (int j = 0; j < 4; j++)
            #pragma unroll
            for (int e = 0; e < 4; e++) ac2[m][j][e] = 0.f;

    #pragma unroll 1
    for (int c = 0; c < 32; c++) {
        const float* bp = g_We + (c * 8 + kx) * 128 + nw2 * 32 + ly * 4;
        float4 q0 = *(const float4*)bp;
        float4 q1 = *(const float4*)(bp + 4 * 128);
        uint32_t B0[4] = {u32(q0.x), u32(q0.y), u32(q0.z), u32(q0.w)};
        uint32_t B1[4] = {u32(q1.x), u32(q1.y), u32(q1.z), u32(q1.w)};
        const float* ap = A + (R2 + ly) * PA + c * 8 + kx;
        uint32_t af0[4] = {u32(ap[0]), u32(ap[8 * PA]), u32(ap[4]), u32(ap[8 * PA + 4])};
        uint32_t af1[4] = {u32(ap[16 * PA]), u32(ap[24 * PA]),
                           u32(ap[16 * PA + 4]), u32(ap[24 * PA + 4])};
        #pragma unroll
        for (int j = 0; j < 4; j++) {
            mma8(ac2[0][j], af0, B0[j], B1[j]);
            mma8(ac2[1][j], af1, B0[j], B1[j]);
        }
    }
    #pragma unroll
    for (int mt = 0; mt < 2; mt++)
        #pragma unroll
        for (int j = 0; j < 4; j++)
            #pragma unroll
            for (int rh = 0; rh < 2; rh++) {
                int row = R2 + mt * 16 + rh * 8 + ly;
                int col = nw2 * 32 + j * 8 + 2 * kx;
                float2 o;
                o.x = fmaxf(ac2[mt][j][rh * 2], 0.f);
                o.y = fmaxf(ac2[mt][j][rh * 2 + 1], 0.f);
                *(float2*)(out + (size_t)(b0 + row) * 128 + col) = o;
            }
}

extern "C" void kernel_launch(void* const* d_in, const int* in_sizes, int n_in,
                              void* d_out, int out_size) {
    prep_kernel<<<128, 512>>>((const float*)d_in[2], (const float*)d_in[3],
                              (const float*)d_in[5], (const float*)d_in[6]);
    cudaFuncSetAttribute(xw_kernel, cudaFuncAttributeMaxDynamicSharedMemorySize, 128 * PX * 4);
    xw_kernel<<<dim3(128, TT), 512, 128 * PX * 4>>>((const float*)d_in[1]);
    cudaFuncSetAttribute(lstm_main, cudaFuncAttributeMaxDynamicSharedMemorySize, SMEM_DYN);
    lstm_main<<<128, 512, SMEM_DYN>>>((const float*)d_in[0], (const float*)d_in[1],
                                      (const float*)d_in[4], (float*)d_out);
}

// round 12
// speedup vs baseline: 3.7044x; 1.0757x over previous
#include <cuda_runtime.h>
#include <cstdint>

#define TT 25
#define PH 132   // h/C/x smem pitch (floats): 132 % 32 == 4 -> conflict-free frags
#define PX 132

__device__ __align__(16) float g_Wk2[128 * 512];  // phase-1 weights, lane-major frag layout
__device__ __align__(16) float g_Wr2[128 * 512];  // recurrent weights, lane-major frag layout
__device__ __align__(16) float g_We[256 * 128];   // output weights (frag-ordered)
__device__ float g_Ho[(size_t)16384 * 128];       // h at t = len-1
__device__ float g_XW[(size_t)16384 * TT * 512];  // x@Wk in accumulator-fragment layout

__device__ __forceinline__ uint32_t tf32r(float v) {
    uint32_t t; asm("cvt.rna.tf32.f32 %0, %1;" : "=r"(t) : "f"(v)); return t;
}
__device__ __forceinline__ float tf32f(float v) { return __uint_as_float(tf32r(v)); }
__device__ __forceinline__ float tanhap(float x) {
    float r; asm("tanh.approx.f32 %0, %1;" : "=f"(r) : "f"(x)); return r;
}
__device__ __forceinline__ float sig_a(float x) { return fmaf(0.5f, tanhap(0.5f * x), 0.5f); }
__device__ __forceinline__ uint32_t u32(float v) { return __float_as_uint(v); }
__device__ __forceinline__ uint32_t smem_u32(const void* p) {
    uint32_t a;
    asm("{.reg .u64 t; cvta.to.shared.u64 t, %1; cvt.u32.u64 %0, t;}" : "=r"(a) : "l"(p));
    return a;
}
__device__ __forceinline__ void cp16(uint32_t dst, const float* src) {
    asm volatile("cp.async.ca.shared.global [%0],[%1],16;" :: "r"(dst), "l"(src) : "memory");
}
#define CP_COMMIT() asm volatile("cp.async.commit_group;" ::: "memory")
#define CP_WAIT0()  asm volatile("cp.async.wait_group 0;" ::: "memory")
#define CP_WAIT1()  asm volatile("cp.async.wait_group 1;" ::: "memory")

__device__ __forceinline__ void mma8(float* d, const uint32_t* a, uint32_t b0, uint32_t b1) {
    asm volatile("mma.sync.aligned.m16n8k8.row.col.f32.tf32.tf32.f32 "
        "{%0,%1,%2,%3},{%4,%5,%6,%7},{%8,%9},{%0,%1,%2,%3};"
        : "+f"(d[0]), "+f"(d[1]), "+f"(d[2]), "+f"(d[3])
        : "r"(a[0]), "r"(a[1]), "r"(a[2]), "r"(a[3]), "r"(b0), "r"(b1));
}

// Lane-major frag layout for K=128 weights: flat f = (((c*4+q)*8+nw)*32+lane)*4+e.
// q=0 -> B0[e], q=1 -> B0[e+4], q=2 -> B1[e], q=3 -> B1[e+4].
// Gate-interleaved logical col: n' = nw*64 + j*8 + ly, source col = (n'&3)*128 + (n'>>2).
__global__ void prep_kernel(const float* __restrict__ Wk, const float* __restrict__ Wr,
                            const float* __restrict__ Ws, const float* __restrict__ Wn) {
    int f = blockIdx.x * blockDim.x + threadIdx.x;   // 65536 threads
    {
        int c = f >> 12, q = (f >> 10) & 3, nw = (f >> 7) & 7, lane = (f >> 2) & 31, e = f & 3;
        int ly = lane >> 2, kx = lane & 3;
        int k = c * 8 + kx + ((q >> 1) << 2);
        int j = (q & 1) ? e + 4 : e;
        int n = nw * 64 + j * 8 + ly;
        int col = (n & 3) * 128 + (n >> 2);
        g_Wk2[f] = tf32f(Wk[k * 512 + col]);
        g_Wr2[f] = tf32f(Wr[k * 512 + col]);
    }
    if (f < 256 * 128) {
        int k = f >> 7, pos = f & 127;
        int nw = pos >> 5, r = pos & 31, ly = r >> 2, j = r & 3;
        int n = nw * 32 + j * 8 + ly;
        float v = (k < 128) ? Ws[k * 128 + n] : Wn[(k - 128) * 128 + n];
        g_We[k * 128 + nw * 32 + ly * 4 + j] = tf32f(v);
    }
}

// ---------------- phase 1: g_XW = x_t @ Wk, 5 timesteps per CTA, cp.async pipelined ----------------
__global__ __launch_bounds__(512, 1)
void xw_kernel(const float* __restrict__ neig) {
    extern __shared__ float X[];   // 2 x [128][PX]
    const int tid = threadIdx.x, wid = tid >> 5, lane = tid & 31;
    const int ly = lane >> 2, kx = lane & 3;
    const int bb = blockIdx.x, t0 = blockIdx.y * 5, b0 = bb * 128;
    const uint32_t Xs = smem_u32(X);

    #pragma unroll
    for (int j2 = 0; j2 < 8; j2++) {
        int i = tid + j2 * 512;
        int r = i >> 5, q = i & 31;
        cp16(Xs + (uint32_t)(r * PX + q * 4) * 4u,
             neig + ((size_t)(b0 + r) * TT + t0) * 128 + q * 4);
    }
    CP_COMMIT();

    #pragma unroll 1
    for (int tt = 0; tt < 5; tt++) {
        const int t = t0 + tt;
        if (tt < 4) {
            const uint32_t dstb = Xs + (uint32_t)(((tt + 1) & 1) * 128 * PX) * 4u;
            #pragma unroll
            for (int j2 = 0; j2 < 8; j2++) {
                int i = tid + j2 * 512;
                int r = i >> 5, q = i & 31;
                cp16(dstb + (uint32_t)(r * PX + q * 4) * 4u,
                     neig + ((size_t)(b0 + r) * TT + t + 1) * 128 + q * 4);
            }
            CP_COMMIT();
            CP_WAIT1();
        } else {
            CP_WAIT0();
        }
        __syncthreads();
        const float* Xb = X + (tt & 1) * 128 * PX;

        const int mw = wid & 1, nw = wid >> 1;
        #pragma unroll 1
        for (int p = 0; p < 2; p++) {
            const int R0 = p * 64 + mw * 32;
            float acc[2][8][4];
            #pragma unroll
            for (int m = 0; m < 2; m++)
                #pragma unroll
                for (int j = 0; j < 8; j++)
                    #pragma unroll
                    for (int e = 0; e < 4; e++) acc[m][j][e] = 0.f;

            const float* wp = g_Wk2 + nw * 128 + lane * 4;
            float4 n0 = *(const float4*)wp,            n1 = *(const float4*)(wp + 1024);
            float4 n2 = *(const float4*)(wp + 2048),   n3 = *(const float4*)(wp + 3072);
            #pragma unroll 1
            for (int c = 0; c < 16; c++) {
                float4 b0v = n0, b1v = n1, b2v = n2, b3v = n3;
                if (c < 15) {
                    const float* np = wp + (c + 1) * 4096;
                    n0 = *(const float4*)np;            n1 = *(const float4*)(np + 1024);
                    n2 = *(const float4*)(np + 2048);   n3 = *(const float4*)(np + 3072);
                }
                const float* ap = Xb + (R0 + ly) * PX + c * 8 + kx;
                uint32_t af0[4] = {u32(ap[0]), u32(ap[8 * PX]), u32(ap[4]), u32(ap[8 * PX + 4])};
                uint32_t af1[4] = {u32(ap[16 * PX]), u32(ap[24 * PX]),
                                   u32(ap[16 * PX + 4]), u32(ap[24 * PX + 4])};
                uint32_t B0[8] = {u32(b0v.x), u32(b0v.y), u32(b0v.z), u32(b0v.w),
                                  u32(b1v.x), u32(b1v.y), u32(b1v.z), u32(b1v.w)};
                uint32_t B1[8] = {u32(b2v.x), u32(b2v.y), u32(b2v.z), u32(b2v.w),
                                  u32(b3v.x), u32(b3v.y), u32(b3v.z), u32(b3v.w)};
                #pragma unroll
                for (int j = 0; j < 8; j++) {
                    mma8(acc[0][j], af0, B0[j], B1[j]);
                    mma8(acc[1][j], af1, B0[j], B1[j]);
                }
            }
            float* op = g_XW + ((((size_t)bb * TT + t) * 2 + p) * 16 + wid) * 2048 + lane * 4;
            #pragma unroll
            for (int i = 0; i < 16; i++)
                *(float4*)(op + i * 128) =
                    make_float4(acc[i >> 3][i & 7][0], acc[i >> 3][i & 7][1],
                                acc[i >> 3][i & 7][2], acc[i >> 3][i & 7][3]);
        }
        __syncthreads();   // all reads of this X buffer done before it is refilled
    }
}

#define SMEM_DYN ((3 * 128 * PH + 512 + 128) * 4)

// ---------------- phase 2: recurrence z = xW + h@Wr (double-buffered h), output GEMM ----------------
__global__ __launch_bounds__(512, 1)
void lstm_main(const float* __restrict__ self_vecs, const float* __restrict__ neig,
               const float* __restrict__ bias, float* __restrict__ out) {
    extern __shared__ float sm[];
    float* H0 = sm;                        // [128][PH] h buffer (even steps read)
    float* H1 = sm + 128 * PH;             // [128][PH] h buffer (odd steps read)
    float* C  = sm + 2 * 128 * PH;         // [128][PH] cell state
    float* biasP = sm + 3 * 128 * PH;      // [512] permuted bias
    int* LEN = (int*)(biasP + 512);

    const int tid = threadIdx.x, wid = tid >> 5, lane = tid & 31;
    const int ly = lane >> 2, kx = lane & 3;
    const int bb = blockIdx.x, b0 = bb * 128;

    for (int i = tid; i < 512; i += 512) biasP[i] = bias[(i & 3) * 128 + (i >> 2)];

    // exact sequence lengths: warp w -> rows w*8..w*8+7
    #pragma unroll
    for (int j = 0; j < 8; j++) {
        int r = wid * 8 + j;
        const float4* xp = (const float4*)(neig + (size_t)(b0 + r) * TT * 128) + lane;
        int cnt = 0;
        for (int t = 0; t < TT; t++) {
            float4 v = xp[t * 32];
            bool nz = v.x != 0.f || v.y != 0.f || v.z != 0.f || v.w != 0.f;
            cnt += (__ballot_sync(~0u, nz) != 0u);
        }
        if (lane == 0) LEN[r] = cnt ? cnt : 1;
    }
    for (int i = tid; i < 128 * 128; i += 512) H0[(i >> 7) * PH + (i & 127)] = 0.f;
    for (int i = tid; i < 128 * PH; i += 512) C[i] = 0.f;

    const int mw = wid & 1, nw = wid >> 1;
    const bool evenlane = (kx & 1) == 0;

    for (int t = 0; t < TT; t++) {
        __syncthreads();   // h writes of step t-1 visible
        const float* hc = (t & 1) ? H1 : H0;
        float*       hn = (t & 1) ? H0 : H1;

        #pragma unroll 1
        for (int p = 0; p < 2; p++) {
            const int R0 = p * 64 + mw * 32;
            // acc init = precomputed x_t@Wk fragment
            float acc[2][8][4];
            {
                const float* xp = g_XW + ((((size_t)bb * TT + t) * 2 + p) * 16 + wid) * 2048
                                + lane * 4;
                #pragma unroll
                for (int i = 0; i < 16; i++) {
                    float4 v = *(const float4*)(xp + i * 128);
                    acc[i >> 3][i & 7][0] = v.x; acc[i >> 3][i & 7][1] = v.y;
                    acc[i >> 3][i & 7][2] = v.z; acc[i >> 3][i & 7][3] = v.w;
                }
            }
            const float* wp = g_Wr2 + nw * 128 + lane * 4;
            float4 n0 = *(const float4*)wp,            n1 = *(const float4*)(wp + 1024);
            float4 n2 = *(const float4*)(wp + 2048),   n3 = *(const float4*)(wp + 3072);
            #pragma unroll 1
            for (int c = 0; c < 16; c++) {
                float4 b0v = n0, b1v = n1, b2v = n2, b3v = n3;
                if (c < 15) {
                    const float* np = wp + (c + 1) * 4096;
                    n0 = *(const float4*)np;            n1 = *(const float4*)(np + 1024);
                    n2 = *(const float4*)(np + 2048);   n3 = *(const float4*)(np + 3072);
                }
                const float* ap = hc + (R0 + ly) * PH + c * 8 + kx;
                uint32_t af0[4] = {u32(ap[0]), u32(ap[8 * PH]), u32(ap[4]), u32(ap[8 * PH + 4])};
                uint32_t af1[4] = {u32(ap[16 * PH]), u32(ap[24 * PH]),
                                   u32(ap[16 * PH + 4]), u32(ap[24 * PH + 4])};
                uint32_t B0[8] = {u32(b0v.x), u32(b0v.y), u32(b0v.z), u32(b0v.w),
                                  u32(b1v.x), u32(b1v.y), u32(b1v.z), u32(b1v.w)};
                uint32_t B1[8] = {u32(b2v.x), u32(b2v.y), u32(b2v.z), u32(b2v.w),
                                  u32(b3v.x), u32(b3v.y), u32(b3v.z), u32(b3v.w)};
                #pragma unroll
                for (int j = 0; j < 8; j++) {
                    mma8(acc[0][j], af0, B0[j], B1[j]);
                    mma8(acc[1][j], af1, B0[j], B1[j]);
                }
            }

            // ---- gate epilogue straight after own GEMM (writes go to hn, no hazard) ----
            #pragma unroll
            for (int mt = 0; mt < 2; mt++) {
                #pragma unroll
                for (int j = 0; j < 8; j++) {
                    const int nn0 = nw * 64 + j * 8 + 2 * kx;
                    const float bz0 = biasP[nn0], bz1 = biasP[nn0 + 1];
                    float z00 = acc[mt][j][0] + bz0;
                    float z01 = acc[mt][j][1] + bz1;
                    float z10 = acc[mt][j][2] + bz0;
                    float z11 = acc[mt][j][3] + bz1;
                    float a00, a01, a10, a11;
                    if (evenlane) { a00 = sig_a(z00);  a01 = sig_a(z01);
                                    a10 = sig_a(z10);  a11 = sig_a(z11); }
                    else          { a00 = tanhap(z00); a01 = sig_a(z01);
                                    a10 = tanhap(z10); a11 = sig_a(z11); }
                    float s1 = evenlane ? a10 : a00;
                    float s2 = evenlane ? a11 : a01;
                    float r1 = __shfl_xor_sync(~0u, s1, 1);
                    float r2 = __shfl_xor_sync(~0u, s2, 1);
                    float iv, fv, gv, ov; int rr;
                    if (evenlane) { iv = a00; fv = a01; gv = r1; ov = r2; rr = R0 + mt * 16 + ly; }
                    else          { iv = r1;  fv = r2;  gv = a10; ov = a11; rr = R0 + mt * 16 + 8 + ly; }
                    const int uu = nw * 16 + j * 2 + (kx >> 1);
                    float cc = fv * C[rr * PH + uu] + iv * gv;
                    C[rr * PH + uu] = cc;
                    float h = ov * tanhap(cc);
                    hn[rr * PH + uu] = tf32f(h);
                    if (t == LEN[rr] - 1) g_Ho[(size_t)(b0 + rr) * 128 + uu] = h;
                }
            }
        }
    }
    __syncthreads();

    // ---- output GEMM: out = relu([self | h_sel] @ We); self -> H0, h_sel -> H1 ----
    for (int i = tid; i < 128 * 32; i += 512) {
        int r = i >> 5, q = i & 31;
        float4 v = *(const float4*)(self_vecs + (size_t)(b0 + r) * 128 + q * 4);
        *(float4*)(H0 + r * PH + q * 4) =
            make_float4(tf32f(v.x), tf32f(v.y), tf32f(v.z), tf32f(v.w));
        float4 h = *(const float4*)(g_Ho + (size_t)(b0 + r) * 128 + q * 4);
        *(float4*)(H1 + r * PH + q * 4) =
            make_float4(tf32f(h.x), tf32f(h.y), tf32f(h.z), tf32f(h.w));
    }
    __syncthreads();

    const int mw2 = wid & 3, nw2 = wid >> 2;   // 4m x 4n warp grid
    const int R2 = mw2 * 32;
    float ac2[2][4][4];
    #pragma unroll
    for (int m = 0; m < 2; m++)
        #pragma unroll
        for (int j = 0; j < 4; j++)
            #pragma unroll
            for (int e = 0; e < 4; e++) ac2[m][j][e] = 0.f;

    #pragma unroll 1
    for (int c = 0; c < 32; c++) {
        const float* bp = g_We + (c * 8 + kx) * 128 + nw2 * 32 + ly * 4;
        float4 q0 = *(const float4*)bp;
        float4 q1 = *(const float4*)(bp + 4 * 128);
        uint32_t B0[4] = {u32(q0.x), u32(q0.y), u32(q0.z), u32(q0.w)};
        uint32_t B1[4] = {u32(q1.x), u32(q1.y), u32(q1.z), u32(q1.w)};
        const float* base = (c < 16) ? H0 : H1;
        const int cc = c & 15;
        const float* ap = base + (R2 + ly) * PH + cc * 8 + kx;
        uint32_t af0[4] = {u32(ap[0]), u32(ap[8 * PH]), u32(ap[4]), u32(ap[8 * PH + 4])};
        uint32_t af1[4] = {u32(ap[16 * PH]), u32(ap[24 * PH]),
                           u32(ap[16 * PH + 4]), u32(ap[24 * PH + 4])};
        #pragma unroll
        for (int j = 0; j < 4; j++) {
            mma8(ac2[0][j], af0, B0[j], B1[j]);
            mma8(ac2[1][j], af1, B0[j], B1[j]);
        }
    }
    #pragma unroll
    for (int mt = 0; mt < 2; mt++)
        #pragma unroll
        for (int j = 0; j < 4; j++)
            #pragma unroll
            for (int rh = 0; rh < 2; rh++) {
                int row = R2 + mt * 16 + rh * 8 + ly;
                int col = nw2 * 32 + j * 8 + 2 * kx;
                float2 o;
                o.x = fmaxf(ac2[mt][j][rh * 2], 0.f);
                o.y = fmaxf(ac2[mt][j][rh * 2 + 1], 0.f);
                *(float2*)(out + (size_t)(b0 + row) * 128 + col) = o;
            }
}

extern "C" void kernel_launch(void* const* d_in, const int* in_sizes, int n_in,
                              void* d_out, int out_size) {
    prep_kernel<<<128, 512>>>((const float*)d_in[2], (const float*)d_in[3],
                              (const float*)d_in[5], (const float*)d_in[6]);
    cudaFuncSetAttribute(xw_kernel, cudaFuncAttributeMaxDynamicSharedMemorySize,
                         2 * 128 * PX * 4);
    xw_kernel<<<dim3(128, 5), 512, 2 * 128 * PX * 4>>>((const float*)d_in[1]);
    cudaFuncSetAttribute(lstm_main, cudaFuncAttributeMaxDynamicSharedMemorySize, SMEM_DYN);
    lstm_main<<<128, 512, SMEM_DYN>>>((const float*)d_in[0], (const float*)d_in[1],
                                      (const float*)d_in[4], (float*)d_out);
}

// round 13
// speedup vs baseline: 3.7158x; 1.0031x over previous
#include <cuda_runtime.h>
#include <cstdint>

#define TT 25
#define PH 132   // h/C/x smem pitch (floats): 132 % 32 == 4 -> conflict-free frags
#define PX 132

__device__ __align__(16) float g_Wk2[128 * 512];  // phase-1 weights, lane-major frag layout
__device__ __align__(16) float g_Wr2[128 * 512];  // recurrent weights, lane-major frag layout
__device__ __align__(16) float g_We[256 * 128];   // output weights (frag-ordered)
__device__ float g_Ho[(size_t)16384 * 128];       // h at t = len-1
__device__ float g_XW[(size_t)16384 * TT * 512];  // x@Wk in accumulator-fragment layout

__device__ __forceinline__ uint32_t tf32r(float v) {
    uint32_t t; asm("cvt.rna.tf32.f32 %0, %1;" : "=r"(t) : "f"(v)); return t;
}
__device__ __forceinline__ float tf32f(float v) { return __uint_as_float(tf32r(v)); }
__device__ __forceinline__ float tanhap(float x) {
    float r; asm("tanh.approx.f32 %0, %1;" : "=f"(r) : "f"(x)); return r;
}
__device__ __forceinline__ float sig_a(float x) { return fmaf(0.5f, tanhap(0.5f * x), 0.5f); }
__device__ __forceinline__ uint32_t u32(float v) { return __float_as_uint(v); }
__device__ __forceinline__ uint32_t smem_u32(const void* p) {
    uint32_t a;
    asm("{.reg .u64 t; cvta.to.shared.u64 t, %1; cvt.u32.u64 %0, t;}" : "=r"(a) : "l"(p));
    return a;
}
__device__ __forceinline__ void cp16(uint32_t dst, const float* src) {
    asm volatile("cp.async.ca.shared.global [%0],[%1],16;" :: "r"(dst), "l"(src) : "memory");
}
#define CP_COMMIT() asm volatile("cp.async.commit_group;" ::: "memory")
#define CP_WAIT0()  asm volatile("cp.async.wait_group 0;" ::: "memory")
#define CP_WAIT1()  asm volatile("cp.async.wait_group 1;" ::: "memory")

__device__ __forceinline__ void mma8(float* d, const uint32_t* a, uint32_t b0, uint32_t b1) {
    asm volatile("mma.sync.aligned.m16n8k8.row.col.f32.tf32.tf32.f32 "
        "{%0,%1,%2,%3},{%4,%5,%6,%7},{%8,%9},{%0,%1,%2,%3};"
        : "+f"(d[0]), "+f"(d[1]), "+f"(d[2]), "+f"(d[3])
        : "r"(a[0]), "r"(a[1]), "r"(a[2]), "r"(a[3]), "r"(b0), "r"(b1));
}

// Lane-major frag layout for K=128 weights: flat f = (((c*4+q)*8+nw)*32+lane)*4+e.
// q=0 -> B0[e], q=1 -> B0[e+4], q=2 -> B1[e], q=3 -> B1[e+4].
// Gate-interleaved logical col: n' = nw*64 + j*8 + ly, source col = (n'&3)*128 + (n'>>2).
__global__ void prep_kernel(const float* __restrict__ Wk, const float* __restrict__ Wr,
                            const float* __restrict__ Ws, const float* __restrict__ Wn) {
    int f = blockIdx.x * blockDim.x + threadIdx.x;   // 65536 threads
    {
        int c = f >> 12, q = (f >> 10) & 3, nw = (f >> 7) & 7, lane = (f >> 2) & 31, e = f & 3;
        int ly = lane >> 2, kx = lane & 3;
        int k = c * 8 + kx + ((q >> 1) << 2);
        int j = (q & 1) ? e + 4 : e;
        int n = nw * 64 + j * 8 + ly;
        int col = (n & 3) * 128 + (n >> 2);
        g_Wk2[f] = tf32f(Wk[k * 512 + col]);
        g_Wr2[f] = tf32f(Wr[k * 512 + col]);
    }
    if (f < 256 * 128) {
        int k = f >> 7, pos = f & 127;
        int nw = pos >> 5, r = pos & 31, ly = r >> 2, j = r & 3;
        int n = nw * 32 + j * 8 + ly;
        float v = (k < 128) ? Ws[k * 128 + n] : Wn[(k - 128) * 128 + n];
        g_We[k * 128 + nw * 32 + ly * 4 + j] = tf32f(v);
    }
}

// ---------------- phase 1: g_XW = x_t @ Wk, 5 timesteps per CTA, cp.async pipelined ----------------
__global__ __launch_bounds__(512, 1)
void xw_kernel(const float* __restrict__ neig) {
    extern __shared__ float X[];   // 2 x [128][PX]
    const int tid = threadIdx.x, wid = tid >> 5, lane = tid & 31;
    const int ly = lane >> 2, kx = lane & 3;
    const int bb = blockIdx.x, t0 = blockIdx.y * 5, b0 = bb * 128;
    const uint32_t Xs = smem_u32(X);

    #pragma unroll
    for (int j2 = 0; j2 < 8; j2++) {
        int i = tid + j2 * 512;
        int r = i >> 5, q = i & 31;
        cp16(Xs + (uint32_t)(r * PX + q * 4) * 4u,
             neig + ((size_t)(b0 + r) * TT + t0) * 128 + q * 4);
    }
    CP_COMMIT();

    #pragma unroll 1
    for (int tt = 0; tt < 5; tt++) {
        const int t = t0 + tt;
        if (tt < 4) {
            const uint32_t dstb = Xs + (uint32_t)(((tt + 1) & 1) * 128 * PX) * 4u;
            #pragma unroll
            for (int j2 = 0; j2 < 8; j2++) {
                int i = tid + j2 * 512;
                int r = i >> 5, q = i & 31;
                cp16(dstb + (uint32_t)(r * PX + q * 4) * 4u,
                     neig + ((size_t)(b0 + r) * TT + t + 1) * 128 + q * 4);
            }
            CP_COMMIT();
            CP_WAIT1();
        } else {
            CP_WAIT0();
        }
        __syncthreads();
        const float* Xb = X + (tt & 1) * 128 * PX;

        const int mw = wid & 1, nw = wid >> 1;
        #pragma unroll 1
        for (int p = 0; p < 2; p++) {
            const int R0 = p * 64 + mw * 32;
            float acc[2][8][4];
            #pragma unroll
            for (int m = 0; m < 2; m++)
                #pragma unroll
                for (int j = 0; j < 8; j++)
                    #pragma unroll
                    for (int e = 0; e < 4; e++) acc[m][j][e] = 0.f;

            const float* wp = g_Wk2 + nw * 128 + lane * 4;
            float4 n0 = *(const float4*)wp,            n1 = *(const float4*)(wp + 1024);
            float4 n2 = *(const float4*)(wp + 2048),   n3 = *(const float4*)(wp + 3072);
            #pragma unroll 1
            for (int c = 0; c < 16; c++) {
                float4 b0v = n0, b1v = n1, b2v = n2, b3v = n3;
                if (c < 15) {
                    const float* np = wp + (c + 1) * 4096;
                    n0 = *(const float4*)np;            n1 = *(const float4*)(np + 1024);
                    n2 = *(const float4*)(np + 2048);   n3 = *(const float4*)(np + 3072);
                }
                const float* ap = Xb + (R0 + ly) * PX + c * 8 + kx;
                uint32_t af0[4] = {u32(ap[0]), u32(ap[8 * PX]), u32(ap[4]), u32(ap[8 * PX + 4])};
                uint32_t af1[4] = {u32(ap[16 * PX]), u32(ap[24 * PX]),
                                   u32(ap[16 * PX + 4]), u32(ap[24 * PX + 4])};
                uint32_t B0[8] = {u32(b0v.x), u32(b0v.y), u32(b0v.z), u32(b0v.w),
                                  u32(b1v.x), u32(b1v.y), u32(b1v.z), u32(b1v.w)};
                uint32_t B1[8] = {u32(b2v.x), u32(b2v.y), u32(b2v.z), u32(b2v.w),
                                  u32(b3v.x), u32(b3v.y), u32(b3v.z), u32(b3v.w)};
                #pragma unroll
                for (int j = 0; j < 8; j++) {
                    mma8(acc[0][j], af0, B0[j], B1[j]);
                    mma8(acc[1][j], af1, B0[j], B1[j]);
                }
            }
            float* op = g_XW + ((((size_t)bb * TT + t) * 2 + p) * 16 + wid) * 2048 + lane * 4;
            #pragma unroll
            for (int i = 0; i < 16; i++)
                *(float4*)(op + i * 128) =
                    make_float4(acc[i >> 3][i & 7][0], acc[i >> 3][i & 7][1],
                                acc[i >> 3][i & 7][2], acc[i >> 3][i & 7][3]);
        }
        __syncthreads();   // all reads of this X buffer done before it is refilled
    }
}

#define SMEM_DYN ((3 * 64 * PH + 512 + 64) * 4)

// ---------------- phase 2: 64 rows/CTA, 256 threads, 2 CTAs co-resident per SM ----------------
__global__ __launch_bounds__(256, 2)
void lstm_main(const float* __restrict__ self_vecs, const float* __restrict__ neig,
               const float* __restrict__ bias, float* __restrict__ out) {
    extern __shared__ float sm[];
    float* H0 = sm;                        // [64][PH] h buffer (even steps read)
    float* H1 = sm + 64 * PH;              // [64][PH] h buffer (odd steps read)
    float* C  = sm + 2 * 64 * PH;          // [64][PH] cell state
    float* biasP = sm + 3 * 64 * PH;       // [512] permuted bias
    int* LEN = (int*)(biasP + 512);

    const int tid = threadIdx.x, wid = tid >> 5, lane = tid & 31;
    const int ly = lane >> 2, kx = lane & 3;
    const int bb = blockIdx.x, b0 = bb * 64;

    for (int i = tid; i < 512; i += 256) biasP[i] = bias[(i & 3) * 128 + (i >> 2)];

    // exact sequence lengths: warp w -> rows w*8..w*8+7 (64 rows total)
    #pragma unroll
    for (int j = 0; j < 8; j++) {
        int r = wid * 8 + j;
        const float4* xp = (const float4*)(neig + (size_t)(b0 + r) * TT * 128) + lane;
        int cnt = 0;
        for (int t = 0; t < TT; t++) {
            float4 v = xp[t * 32];
            bool nz = v.x != 0.f || v.y != 0.f || v.z != 0.f || v.w != 0.f;
            cnt += (__ballot_sync(~0u, nz) != 0u);
        }
        if (lane == 0) LEN[r] = cnt ? cnt : 1;
    }
    for (int i = tid; i < 64 * 128; i += 256) H0[(i >> 7) * PH + (i & 127)] = 0.f;
    for (int i = tid; i < 64 * PH; i += 256) C[i] = 0.f;

    const int nw = wid;                    // 8 warps, each owns 64 output cols
    const bool evenlane = (kx & 1) == 0;
    // xW fragment base: this CTA is old CTA (bb>>1), old m-pass (bb&1)
    const size_t xwcta = (((size_t)(bb >> 1) * TT) * 2 + (bb & 1)) * 16;

    for (int t = 0; t < TT; t++) {
        __syncthreads();   // h writes of step t-1 visible
        const float* hc = (t & 1) ? H1 : H0;
        float*       hn = (t & 1) ? H0 : H1;

        #pragma unroll 1
        for (int p = 0; p < 2; p++) {      // two 32-row m-passes within the 64
            const int R0 = p * 32;
            float acc[2][8][4];
            {   // acc init = precomputed x_t@Wk fragment (old wid = p + nw*2)
                const float* xp = g_XW + (xwcta + (size_t)t * 32 + (p + nw * 2)) * 2048
                                + lane * 4;
                #pragma unroll
                for (int i = 0; i < 16; i++) {
                    float4 v = *(const float4*)(xp + i * 128);
                    acc[i >> 3][i & 7][0] = v.x; acc[i >> 3][i & 7][1] = v.y;
                    acc[i >> 3][i & 7][2] = v.z; acc[i >> 3][i & 7][3] = v.w;
                }
            }
            const float* wp = g_Wr2 + nw * 128 + lane * 4;
            float4 n0 = *(const float4*)wp,            n1 = *(const float4*)(wp + 1024);
            float4 n2 = *(const float4*)(wp + 2048),   n3 = *(const float4*)(wp + 3072);
            #pragma unroll 1
            for (int c = 0; c < 16; c++) {
                float4 b0v = n0, b1v = n1, b2v = n2, b3v = n3;
                if (c < 15) {
                    const float* np = wp + (c + 1) * 4096;
                    n0 = *(const float4*)np;            n1 = *(const float4*)(np + 1024);
                    n2 = *(const float4*)(np + 2048);   n3 = *(const float4*)(np + 3072);
                }
                const float* ap = hc + (R0 + ly) * PH + c * 8 + kx;
                uint32_t af0[4] = {u32(ap[0]), u32(ap[8 * PH]), u32(ap[4]), u32(ap[8 * PH + 4])};
                uint32_t af1[4] = {u32(ap[16 * PH]), u32(ap[24 * PH]),
                                   u32(ap[16 * PH + 4]), u32(ap[24 * PH + 4])};
                uint32_t B0[8] = {u32(b0v.x), u32(b0v.y), u32(b0v.z), u32(b0v.w),
                                  u32(b1v.x), u32(b1v.y), u32(b1v.z), u32(b1v.w)};
                uint32_t B1[8] = {u32(b2v.x), u32(b2v.y), u32(b2v.z), u32(b2v.w),
                                  u32(b3v.x), u32(b3v.y), u32(b3v.z), u32(b3v.w)};
                #pragma unroll
                for (int j = 0; j < 8; j++) {
                    mma8(acc[0][j], af0, B0[j], B1[j]);
                    mma8(acc[1][j], af1, B0[j], B1[j]);
                }
            }

            // ---- gate epilogue straight after own GEMM (writes hn, no hazard) ----
            #pragma unroll
            for (int mt = 0; mt < 2; mt++) {
                #pragma unroll
                for (int j = 0; j < 8; j++) {
                    const int nn0 = nw * 64 + j * 8 + 2 * kx;
                    const float bz0 = biasP[nn0], bz1 = biasP[nn0 + 1];
                    float z00 = acc[mt][j][0] + bz0;
                    float z01 = acc[mt][j][1] + bz1;
                    float z10 = acc[mt][j][2] + bz0;
                    float z11 = acc[mt][j][3] + bz1;
                    float a00, a01, a10, a11;
                    if (evenlane) { a00 = sig_a(z00);  a01 = sig_a(z01);
                                    a10 = sig_a(z10);  a11 = sig_a(z11); }
                    else          { a00 = tanhap(z00); a01 = sig_a(z01);
                                    a10 = tanhap(z10); a11 = sig_a(z11); }
                    float s1 = evenlane ? a10 : a00;
                    float s2 = evenlane ? a11 : a01;
                    float r1 = __shfl_xor_sync(~0u, s1, 1);
                    float r2 = __shfl_xor_sync(~0u, s2, 1);
                    float iv, fv, gv, ov; int rr;
                    if (evenlane) { iv = a00; fv = a01; gv = r1; ov = r2; rr = R0 + mt * 16 + ly; }
                    else          { iv = r1;  fv = r2;  gv = a10; ov = a11; rr = R0 + mt * 16 + 8 + ly; }
                    const int uu = nw * 16 + j * 2 + (kx >> 1);
                    float cc = fv * C[rr * PH + uu] + iv * gv;
                    C[rr * PH + uu] = cc;
                    float h = ov * tanhap(cc);
                    hn[rr * PH + uu] = tf32f(h);
                    if (t == LEN[rr] - 1) g_Ho[(size_t)(b0 + rr) * 128 + uu] = h;
                }
            }
        }
    }
    __syncthreads();

    // ---- output GEMM: out = relu([self | h_sel] @ We); self -> H0, h_sel -> H1 ----
    for (int i = tid; i < 64 * 32; i += 256) {
        int r = i >> 5, q = i & 31;
        float4 v = *(const float4*)(self_vecs + (size_t)(b0 + r) * 128 + q * 4);
        *(float4*)(H0 + r * PH + q * 4) =
            make_float4(tf32f(v.x), tf32f(v.y), tf32f(v.z), tf32f(v.w));
        float4 h = *(const float4*)(g_Ho + (size_t)(b0 + r) * 128 + q * 4);
        *(float4*)(H1 + r * PH + q * 4) =
            make_float4(tf32f(h.x), tf32f(h.y), tf32f(h.z), tf32f(h.w));
    }
    __syncthreads();

    const int mw2 = wid & 1, nw2 = wid >> 1;   // 2m x 4n warp grid over 64 rows
    const int R2 = mw2 * 32;
    float ac2[2][4][4];
    #pragma unroll
    for (int m = 0; m < 2; m++)
        #pragma unroll
        for (int j = 0; j < 4; j++)
            #pragma unroll
            for (int e = 0; e < 4; e++) ac2[m][j][e] = 0.f;

    #pragma unroll 1
    for (int c = 0; c < 32; c++) {
        const float* bp = g_We + (c * 8 + kx) * 128 + nw2 * 32 + ly * 4;
        float4 q0 = *(const float4*)bp;
        float4 q1 = *(const float4*)(bp + 4 * 128);
        uint32_t B0[4] = {u32(q0.x), u32(q0.y), u32(q0.z), u32(q0.w)};
        uint32_t B1[4] = {u32(q1.x), u32(q1.y), u32(q1.z), u32(q1.w)};
        const float* base = (c < 16) ? H0 : H1;
        const int cc = c & 15;
        const float* ap = base + (R2 + ly) * PH + cc * 8 + kx;
        uint32_t af0[4] = {u32(ap[0]), u32(ap[8 * PH]), u32(ap[4]), u32(ap[8 * PH + 4])};
        uint32_t af1[4] = {u32(ap[16 * PH]), u32(ap[24 * PH]),
                           u32(ap[16 * PH + 4]), u32(ap[24 * PH + 4])};
        #pragma unroll
        for (int j = 0; j < 4; j++) {
            mma8(ac2[0][j], af0, B0[j], B1[j]);
            mma8(ac2[1][j], af1, B0[j], B1[j]);
        }
    }
    #pragma unroll
    for (int mt = 0; mt < 2; mt++)
        #pragma unroll
        for (int j = 0; j < 4; j++)
            #pragma unroll
            for (int rh = 0; rh < 2; rh++) {
                int row = R2 + mt * 16 + rh * 8 + ly;
                int col = nw2 * 32 + j * 8 + 2 * kx;
                float2 o;
                o.x = fmaxf(ac2[mt][j][rh * 2], 0.f);
                o.y = fmaxf(ac2[mt][j][rh * 2 + 1], 0.f);
                *(float2*)(out + (size_t)(b0 + row) * 128 + col) = o;
            }
}

extern "C" void kernel_launch(void* const* d_in, const int* in_sizes, int n_in,
                              void* d_out, int out_size) {
    prep_kernel<<<128, 512>>>((const float*)d_in[2], (const float*)d_in[3],
                              (const float*)d_in[5], (const float*)d_in[6]);
    cudaFuncSetAttribute(xw_kernel, cudaFuncAttributeMaxDynamicSharedMemorySize,
                         2 * 128 * PX * 4);
    xw_kernel<<<dim3(128, 5), 512, 2 * 128 * PX * 4>>>((const float*)d_in[1]);
    cudaFuncSetAttribute(lstm_main, cudaFuncAttributeMaxDynamicSharedMemorySize, SMEM_DYN);
    lstm_main<<<256, 256, SMEM_DYN>>>((const float*)d_in[0], (const float*)d_in[1],
                                      (const float*)d_in[4], (float*)d_out);
}